// round 2
// baseline (speedup 1.0000x reference)
#include <cuda_runtime.h>

// Ende_3332894622093: B=65536, D=40, HB=20.
// out = [t1 | s2] (B,1,40);  J_T (B,40,40) =
//   [[diag(e4)+JJ12@J21, JJ12*e2], [J21, diag(e2)]]
// d_out: out flattened (n*40) then J_T flattened (n*1600).

#define NW 8  // warps (=batch items) per block

struct WarpSmem {
    float  xs[40];     // input row, later reused to stage [t1|s2]
    float2 bb[20];     // (b1, b2) per k
    float  s2s[20];    // s2 vector
    float  e2s[20];
    float  e4s[20];
    float  jjs[400];   // JJ12 row-major (i,k), stride 20
    float  j21[400];   // J21  row-major (k,j), stride 20
};

__global__ __launch_bounds__(NW * 32)
void ende_kernel(const float* __restrict__ src,
                 const float* __restrict__ w1,
                 const float* __restrict__ w2,
                 const float* __restrict__ w3,
                 const float* __restrict__ w4,
                 float* __restrict__ outp,
                 float* __restrict__ jt,
                 int n)
{
    __shared__ float w1s[400], w2s[400], w3s[400], w4s[400];
    __shared__ WarpSmem ws[NW];

    const int tid = threadIdx.x;
    for (int i = tid; i < 400; i += NW * 32) {
        w1s[i] = w1[i];
        w2s[i] = w2[i];
        w3s[i] = w3[i];
        w4s[i] = w4[i];
    }
    __syncthreads();

    const int warp = tid >> 5;
    const int lane = tid & 31;
    const int b = blockIdx.x * NW + warp;
    if (b >= n) return;

    WarpSmem& S = ws[warp];

    // ---- load x (40 floats = 10 float4) ----
    const float4* xg = (const float4*)(src + (size_t)b * 40);
    if (lane < 10) ((float4*)S.xs)[lane] = xg[lane];
    __syncwarp();

    const int j = lane;

    // ---- phase B: f1, f2, e2, (b1,b2), s2 ----
    if (j < 20) {
        float acc1 = 0.f, acc2 = 0.f;
        const float4* xv  = (const float4*)S.xs;          // p1 broadcast
        const float4* w1r = (const float4*)&w1s[j * 20];
        const float4* w2r = (const float4*)&w2s[j * 20];
        #pragma unroll
        for (int k4 = 0; k4 < 5; k4++) {
            float4 xx = xv[k4], a = w1r[k4], c = w2r[k4];
            acc1 += xx.x * a.x + xx.y * a.y + xx.z * a.z + xx.w * a.w;
            acc2 += xx.x * c.x + xx.y * c.y + xx.z * c.z + xx.w * c.w;
        }
        float f1 = tanhf(acc1);
        float f2 = tanhf(acc2);
        float e2 = expf(f2);
        float p2  = S.xs[20 + j];
        float p2e = p2 * e2;
        float s2  = p2e + f1;
        S.bb[j]  = make_float2(1.f - f1 * f1, p2e * (1.f - f2 * f2));
        S.s2s[j] = s2;
        S.e2s[j] = e2;
    }
    __syncwarp();

    // ---- phase C: f3, f4, e4, t1, JJ12 row j ----
    if (j < 20) {
        float acc3 = 0.f, acc4 = 0.f;
        const float4* sv  = (const float4*)S.s2s;         // s2 broadcast
        const float4* w3r = (const float4*)&w3s[j * 20];
        const float4* w4r = (const float4*)&w4s[j * 20];
        #pragma unroll
        for (int k4 = 0; k4 < 5; k4++) {
            float4 xx = sv[k4], a = w3r[k4], c = w4r[k4];
            acc3 += xx.x * a.x + xx.y * a.y + xx.z * a.z + xx.w * a.w;
            acc4 += xx.x * c.x + xx.y * c.y + xx.z * c.z + xx.w * c.w;
        }
        float f3 = tanhf(acc3);
        float f4 = tanhf(acc4);
        float e4 = expf(f4);
        float s1  = S.xs[j];
        float s1e = s1 * e4;
        float a3 = 1.f - f3 * f3;
        float a4 = s1e * (1.f - f4 * f4);
        float4* jj = (float4*)&S.jjs[j * 20];
        #pragma unroll
        for (int k4 = 0; k4 < 5; k4++) {
            float4 a_ = w3r[k4], c_ = w4r[k4], r;
            r.x = a3 * a_.x + a4 * c_.x;
            r.y = a3 * a_.y + a4 * c_.y;
            r.z = a3 * a_.z + a4 * c_.z;
            r.w = a3 * a_.w + a4 * c_.w;
            jj[k4] = r;
        }
        S.e4s[j] = e4;
        // stage output row in xs (safe: each lane reads only xs[j], xs[20+j] already consumed)
        S.xs[j]      = s1e + f3;   // t1
        S.xs[20 + j] = S.s2s[j];   // s2
    }
    __syncwarp();

    float* J = jt + (size_t)b * 1600;

    // ---- out row: 10-lane STG.128 ----
    if (lane < 10) {
        float4 ov = ((const float4*)S.xs)[lane];
        __stcs((float4*)(outp + (size_t)b * 40) + lane, ov);
    }

    // ---- phase D: bottom half (J21 rows + diag(e2)), all 32 lanes, float4 tasks ----
    #pragma unroll
    for (int it = 0; it < 4; it++) {
        int t = lane + it * 32;
        if (t < 100) {
            int k = t / 5, c = t % 5;
            float2 bv = S.bb[k];
            float4 wa = *(const float4*)&w1s[k * 20 + 4 * c];
            float4 wb = *(const float4*)&w2s[k * 20 + 4 * c];
            float4 r;
            r.x = bv.x * wa.x + bv.y * wb.x;
            r.y = bv.x * wa.y + bv.y * wb.y;
            r.z = bv.x * wa.z + bv.y * wb.z;
            r.w = bv.x * wa.w + bv.y * wb.w;
            *(float4*)&S.j21[k * 20 + 4 * c] = r;
            __stcs((float4*)&J[(20 + k) * 40 + 4 * c], r);
            float4 z = make_float4(0.f, 0.f, 0.f, 0.f);
            if (k >= 4 * c && k < 4 * c + 4)
                ((float*)&z)[k - 4 * c] = S.e2s[k];
            __stcs((float4*)&J[(20 + k) * 40 + 20 + 4 * c], z);
        }
    }
    __syncwarp();

    // ---- phase E: top half (TL = diag(e4) + JJ12@J21, TR = JJ12*e2), float4 tasks ----
    #pragma unroll
    for (int it = 0; it < 4; it++) {
        int t = lane + it * 32;
        if (t < 100) {
            int i = t / 5, c = t % 5;
            // TR
            float4 jjv = *(const float4*)&S.jjs[i * 20 + 4 * c];
            float4 e2v = *(const float4*)&S.e2s[4 * c];
            float4 tr;
            tr.x = jjv.x * e2v.x; tr.y = jjv.y * e2v.y;
            tr.z = jjv.z * e2v.z; tr.w = jjv.w * e2v.w;
            __stcs((float4*)&J[i * 40 + 20 + 4 * c], tr);
            // TL
            float4 acc = make_float4(0.f, 0.f, 0.f, 0.f);
            #pragma unroll
            for (int k4 = 0; k4 < 5; k4++) {
                float4 jj4 = *(const float4*)&S.jjs[i * 20 + 4 * k4];
                #pragma unroll
                for (int kk = 0; kk < 4; kk++) {
                    float s = ((const float*)&jj4)[kk];
                    float4 jv = *(const float4*)&S.j21[(4 * k4 + kk) * 20 + 4 * c];
                    acc.x += s * jv.x;
                    acc.y += s * jv.y;
                    acc.z += s * jv.z;
                    acc.w += s * jv.w;
                }
            }
            if (i >= 4 * c && i < 4 * c + 4)
                ((float*)&acc)[i - 4 * c] += S.e4s[i];
            __stcs((float4*)&J[i * 40 + 4 * c], acc);
        }
    }
}

extern "C" void kernel_launch(void* const* d_in, const int* in_sizes, int n_in,
                              void* d_out, int out_size)
{
    const float* src = (const float*)d_in[0];
    const float* w1  = (const float*)d_in[1];
    const float* w2  = (const float*)d_in[2];
    const float* w3  = (const float*)d_in[3];
    const float* w4  = (const float*)d_in[4];

    int n = in_sizes[0] / 40;
    float* outp = (float*)d_out;
    float* jt   = (float*)d_out + (size_t)n * 40;

    int blocks = (n + NW - 1) / NW;
    ende_kernel<<<blocks, NW * 32>>>(src, w1, w2, w3, w4, outp, jt, n);
}

// round 3
// speedup vs baseline: 1.4127x; 1.4127x over previous
#include <cuda_runtime.h>

// Ende_3332894622093: B=65536, D=40, HB=20.
// out = [t1 | s2] (B,1,40);  J_T (B,40,40) =
//   [[diag(e4)+JJ12@J21, JJ12*e2], [J21, diag(e2)]]
// d_out: out flattened (n*40) then J_T flattened (n*1600).
//
// Mapping: thread -> (item = tid/20, j = tid%20). 20 threads per item, zero
// idle lanes. Per-item smem region stride 528 floats (== 16 banks mod 32) so
// the two items sharing a warp broadcast from disjoint banks.

#define IPB 16            // items per block
#define TPB (IPB * 20)    // 320 threads
#define WSS 528           // per-item smem stride (floats)
// per-item layout: xs[0..40), bb[40..80) (float2 x20), s2s[80..100), jjs[100..500)

__global__ __launch_bounds__(TPB)
void ende_kernel(const float* __restrict__ src,
                 const float* __restrict__ w1,
                 const float* __restrict__ w2,
                 const float* __restrict__ w3,
                 const float* __restrict__ w4,
                 float* __restrict__ outp,
                 float* __restrict__ jt,
                 int n)
{
    __shared__ float w1s[400], w2s[400], w3s[400], w4s[400];
    __shared__ __align__(16) float ws[IPB * WSS];

    const int tid = threadIdx.x;
    for (int i = tid; i < 400; i += TPB) {
        w1s[i] = w1[i];
        w2s[i] = w2[i];
        w3s[i] = w3[i];
        w4s[i] = w4[i];
    }

    const int itemL = tid / 20;
    const int j     = tid % 20;
    const int b     = blockIdx.x * IPB + itemL;
    const bool act  = (b < n);
    float* S = &ws[itemL * WSS];

    // ---- cooperative x load: 160 float4 = 16 items x 40 floats ----
    if (tid < IPB * 10) {
        int it = tid / 10, c = tid % 10;
        if (blockIdx.x * IPB + it < n) {
            float4 v = ((const float4*)(src + (size_t)(blockIdx.x * IPB + it) * 40))[c];
            *(float4*)&ws[it * WSS + c * 4] = v;
        }
    }
    __syncthreads();

    // ---- phase B: f1, f2, e2, (b1,b2), s2 ----
    float e2j, s2j;
    {
        float acc1 = 0.f, acc2 = 0.f;
        const float4* xv  = (const float4*)S;
        const float4* w1r = (const float4*)&w1s[j * 20];
        const float4* w2r = (const float4*)&w2s[j * 20];
        #pragma unroll
        for (int k4 = 0; k4 < 5; k4++) {
            float4 xx = xv[k4], a = w1r[k4], c = w2r[k4];
            acc1 += xx.x * a.x + xx.y * a.y + xx.z * a.z + xx.w * a.w;
            acc2 += xx.x * c.x + xx.y * c.y + xx.z * c.z + xx.w * c.w;
        }
        float f1 = tanhf(acc1);
        float f2 = tanhf(acc2);
        e2j = expf(f2);
        float p2  = S[20 + j];
        float p2e = p2 * e2j;
        s2j = p2e + f1;
        ((float2*)&S[40])[j] = make_float2(1.f - f1 * f1, p2e * (1.f - f2 * f2));
        S[80 + j] = s2j;
    }
    __syncthreads();

    // ---- phase C: f3, f4, e4, t1, JJ12 row j ----
    float e4j;
    {
        float acc3 = 0.f, acc4 = 0.f;
        const float4* sv  = (const float4*)&S[80];
        const float4* w3r = (const float4*)&w3s[j * 20];
        const float4* w4r = (const float4*)&w4s[j * 20];
        #pragma unroll
        for (int k4 = 0; k4 < 5; k4++) {
            float4 xx = sv[k4], a = w3r[k4], c = w4r[k4];
            acc3 += xx.x * a.x + xx.y * a.y + xx.z * a.z + xx.w * a.w;
            acc4 += xx.x * c.x + xx.y * c.y + xx.z * c.z + xx.w * c.w;
        }
        float f3 = tanhf(acc3);
        float f4 = tanhf(acc4);
        e4j = expf(f4);
        float s1  = S[j];
        float s1e = s1 * e4j;
        float a3 = 1.f - f3 * f3;
        float a4 = s1e * (1.f - f4 * f4);
        float4* jj = (float4*)&S[100 + j * 20];
        #pragma unroll
        for (int k4 = 0; k4 < 5; k4++) {
            float4 a_ = w3r[k4], c_ = w4r[k4], r;
            r.x = a3 * a_.x + a4 * c_.x;
            r.y = a3 * a_.y + a4 * c_.y;
            r.z = a3 * a_.z + a4 * c_.z;
            r.w = a3 * a_.w + a4 * c_.w;
            jj[k4] = r;
        }
        if (act) {
            outp[(size_t)b * 40 + j]      = s1e + f3;  // t1
            outp[(size_t)b * 40 + 20 + j] = s2j;
        }
    }
    __syncthreads();

    float* J = jt + (size_t)b * 1600;
    const int part = (j & 1) ? (tid - 1) : (tid + 1);  // same-item, same-warp partner
    const bool odd = (j & 1);

    // ---- phase D: my_col = J21 column j; store BL|BR full rows (STG.64 pairs) ----
    float my_col[20];
    #pragma unroll
    for (int kk = 0; kk < 10; kk++) {
        float4 bbp = *(const float4*)&S[40 + 4 * kk];   // (b1,b2) for k=2kk, 2kk+1
        #pragma unroll
        for (int s = 0; s < 2; s++) {
            int k = 2 * kk + s;
            float b1v = s ? bbp.z : bbp.x;
            float b2v = s ? bbp.w : bbp.y;
            float c = b1v * w1s[k * 20 + j] + b2v * w2s[k * 20 + j];
            my_col[k] = c;
            float brv = (k == j) ? e2j : 0.f;
            float pc  = __shfl_sync(0xFFFFFFFFu, c,   part);
            float pbr = __shfl_sync(0xFFFFFFFFu, brv, part);
            if (act) {
                if (odd)
                    __stcs((float2*)&J[(20 + k) * 40 + 20 + (j - 1)], make_float2(pbr, brv));
                else
                    __stcs((float2*)&J[(20 + k) * 40 + j], make_float2(c, pc));
            }
        }
    }

    // ---- phase E: TL = diag(e4)+JJ12@J21, TR = JJ12*e2; full-row STG.64 pairs ----
    #pragma unroll 4
    for (int i = 0; i < 20; i++) {
        const float4* jjr = (const float4*)&S[100 + i * 20];
        float acc = 0.f;
        #pragma unroll
        for (int k4 = 0; k4 < 5; k4++) {
            float4 v = jjr[k4];
            acc += v.x * my_col[4 * k4 + 0] + v.y * my_col[4 * k4 + 1]
                 + v.z * my_col[4 * k4 + 2] + v.w * my_col[4 * k4 + 3];
        }
        if (i == j) acc += e4j;
        float trv = S[100 + i * 20 + j] * e2j;
        float pacc = __shfl_sync(0xFFFFFFFFu, acc, part);
        float ptr  = __shfl_sync(0xFFFFFFFFu, trv, part);
        if (act) {
            if (odd)
                __stcs((float2*)&J[i * 40 + 20 + (j - 1)], make_float2(ptr, trv));
            else
                __stcs((float2*)&J[i * 40 + j], make_float2(acc, pacc));
        }
    }
}

extern "C" void kernel_launch(void* const* d_in, const int* in_sizes, int n_in,
                              void* d_out, int out_size)
{
    const float* src = (const float*)d_in[0];
    const float* w1  = (const float*)d_in[1];
    const float* w2  = (const float*)d_in[2];
    const float* w3  = (const float*)d_in[3];
    const float* w4  = (const float*)d_in[4];

    int n = in_sizes[0] / 40;
    float* outp = (float*)d_out;
    float* jt   = (float*)d_out + (size_t)n * 40;

    int blocks = (n + IPB - 1) / IPB;
    ende_kernel<<<blocks, TPB>>>(src, w1, w2, w3, w4, outp, jt, n);
}